// round 2
// baseline (speedup 1.0000x reference)
#include <cuda_runtime.h>
#include <math.h>

#define NMAX 100000
#define EMAX 3200000
#define HDIM 64

// ---------------- static device scratch (no dynamic allocation allowed) ----------------
__device__ int   g_src[EMAX];
__device__ int   g_dst[EMAX];
__device__ int2  g_cedge[EMAX];          // packed {src, norm_weight_as_int}
__device__ int   g_cnt[NMAX];
__device__ int   g_off[NMAX + 1];
__device__ int   g_pos[NMAX];
__device__ float g_dis[NMAX];
__device__ __align__(16) float g_bufL[(size_t)NMAX * HDIM];
__device__ __align__(16) float g_bufH[(size_t)NMAX * HDIM];

// ---------------- prep kernels ----------------
__global__ void k_zero_cnt(int n) {
    int i = blockIdx.x * blockDim.x + threadIdx.x;
    if (i < n) g_cnt[i] = 0;
}

// edge index is int32 (JAX x64 disabled); histogram in-degree
__global__ void k_edges1(const int* __restrict__ ei, int E, int n) {
    int e = blockIdx.x * blockDim.x + threadIdx.x;
    if (e >= E) return;
    int s = ei[e];
    int d = ei[(size_t)E + e];
    s = min(max(s, 0), n - 1);   // defensive clamp, branch-free
    d = min(max(d, 0), n - 1);
    g_src[e] = s;
    g_dst[e] = d;
    atomicAdd(&g_cnt[d], 1);
}

// deg = in_degree + 1 (self loop); dis = deg^-1/2 (deg >= 1 always)
__global__ void k_dis(int n) {
    int i = blockIdx.x * blockDim.x + threadIdx.x;
    if (i < n) g_dis[i] = rsqrtf((float)g_cnt[i] + 1.0f);
}

// single-block chunked exclusive scan of g_cnt -> g_off, g_pos
__global__ void k_scan(int n) {
    __shared__ int ssum[1024];
    int t = threadIdx.x;
    int chunk = (n + 1023) >> 10;
    int s0 = t * chunk; if (s0 > n) s0 = n;
    int s1 = s0 + chunk; if (s1 > n) s1 = n;
    int s = 0;
    for (int i = s0; i < s1; i++) s += g_cnt[i];
    ssum[t] = s;
    __syncthreads();
    for (int off = 1; off < 1024; off <<= 1) {
        int v = (t >= off) ? ssum[t - off] : 0;
        __syncthreads();
        ssum[t] += v;
        __syncthreads();
    }
    int run = (t > 0) ? ssum[t - 1] : 0;
    for (int i = s0; i < s1; i++) {
        g_off[i] = run;
        g_pos[i] = run;
        run += g_cnt[i];
    }
    if (s1 == n) g_off[n] = run;   // all covering threads write the same total
}

// scatter edges into CSR-by-dst; pack src + precomputed norm weight into 8B
__global__ void k_scatter(int E) {
    int e = blockIdx.x * blockDim.x + threadIdx.x;
    if (e >= E) return;
    int s = g_src[e];
    int d = g_dst[e];
    int p = atomicAdd(&g_pos[d], 1);
    float w = g_dis[s] * g_dis[d];
    g_cedge[p] = make_int2(s, __float_as_int(w));
}

// ---------------- dense GEMM: C[n,64] = A[n,K] @ W[K,64] ----------------
// 64-row tiles, 4x4 register blocking, K chunked by 64 to stay under 48KB static smem.
template <int K>
__global__ void __launch_bounds__(256) k_gemm(const float* __restrict__ A,
                                              const float* __restrict__ W,
                                              float* __restrict__ C, int n) {
    __shared__ float Ws[K * 64];
    __shared__ float As[64 * 64];
    int tid = threadIdx.x;
    int rowBase = blockIdx.x * 64;
    for (int idx = tid; idx < K * 64; idx += 256) Ws[idx] = W[idx];

    int tc = tid & 15;       // 16 col groups of 4
    int tr = tid >> 4;       // 16 row groups of 4
    float acc[4][4];
#pragma unroll
    for (int i = 0; i < 4; i++)
#pragma unroll
        for (int j = 0; j < 4; j++) acc[i][j] = 0.0f;

    for (int kk = 0; kk < K; kk += 64) {
        __syncthreads();
        for (int idx = tid; idx < 64 * 64; idx += 256) {
            int r = idx >> 6, c = idx & 63;
            int gr = rowBase + r;
            As[idx] = (gr < n) ? A[(size_t)gr * K + kk + c] : 0.0f;
        }
        __syncthreads();
#pragma unroll 8
        for (int k2 = 0; k2 < 64; k2++) {
            float4 wv = *(const float4*)&Ws[(kk + k2) * 64 + tc * 4];
            float a0 = As[(tr * 4 + 0) * 64 + k2];
            float a1 = As[(tr * 4 + 1) * 64 + k2];
            float a2 = As[(tr * 4 + 2) * 64 + k2];
            float a3 = As[(tr * 4 + 3) * 64 + k2];
            acc[0][0] = fmaf(a0, wv.x, acc[0][0]); acc[0][1] = fmaf(a0, wv.y, acc[0][1]);
            acc[0][2] = fmaf(a0, wv.z, acc[0][2]); acc[0][3] = fmaf(a0, wv.w, acc[0][3]);
            acc[1][0] = fmaf(a1, wv.x, acc[1][0]); acc[1][1] = fmaf(a1, wv.y, acc[1][1]);
            acc[1][2] = fmaf(a1, wv.z, acc[1][2]); acc[1][3] = fmaf(a1, wv.w, acc[1][3]);
            acc[2][0] = fmaf(a2, wv.x, acc[2][0]); acc[2][1] = fmaf(a2, wv.y, acc[2][1]);
            acc[2][2] = fmaf(a2, wv.z, acc[2][2]); acc[2][3] = fmaf(a2, wv.w, acc[2][3]);
            acc[3][0] = fmaf(a3, wv.x, acc[3][0]); acc[3][1] = fmaf(a3, wv.y, acc[3][1]);
            acc[3][2] = fmaf(a3, wv.z, acc[3][2]); acc[3][3] = fmaf(a3, wv.w, acc[3][3]);
        }
    }
#pragma unroll
    for (int i = 0; i < 4; i++) {
        int gr = rowBase + tr * 4 + i;
        if (gr < n) {
            float4 o = make_float4(acc[i][0], acc[i][1], acc[i][2], acc[i][3]);
            *(float4*)&C[((size_t)gr << 6) + tc * 4] = o;
        }
    }
}

// ---------------- pull-based aggregation + bias + self-loop + tanh ----------------
// 16 lanes per node; each lane owns 4 columns (float4).
__global__ void __launch_bounds__(256) k_agg(const float* __restrict__ L,
                                             const float* __restrict__ bias,
                                             float* __restrict__ Out, int n) {
    int t = blockIdx.x * blockDim.x + threadIdx.x;
    int node = t >> 4;
    if (node >= n) return;
    int c4 = (t & 15) << 2;

    float dn = g_dis[node];
    float ws = dn * dn;
    float4 bv = *(const float4*)&bias[c4];
    float4 sv = *(const float4*)&L[((size_t)node << 6) + c4];
    float4 acc = make_float4(fmaf(sv.x, ws, bv.x), fmaf(sv.y, ws, bv.y),
                             fmaf(sv.z, ws, bv.z), fmaf(sv.w, ws, bv.w));

    int e    = g_off[node];
    int eEnd = g_off[node + 1];
    for (; e + 2 <= eEnd; e += 2) {
        int2 ed0 = g_cedge[e];
        int2 ed1 = g_cedge[e + 1];
        float w0 = __int_as_float(ed0.y);
        float w1 = __int_as_float(ed1.y);
        float4 v0 = *(const float4*)&L[((size_t)ed0.x << 6) + c4];
        float4 v1 = *(const float4*)&L[((size_t)ed1.x << 6) + c4];
        acc.x = fmaf(v0.x, w0, acc.x); acc.y = fmaf(v0.y, w0, acc.y);
        acc.z = fmaf(v0.z, w0, acc.z); acc.w = fmaf(v0.w, w0, acc.w);
        acc.x = fmaf(v1.x, w1, acc.x); acc.y = fmaf(v1.y, w1, acc.y);
        acc.z = fmaf(v1.z, w1, acc.z); acc.w = fmaf(v1.w, w1, acc.w);
    }
    if (e < eEnd) {
        int2 ed = g_cedge[e];
        float w = __int_as_float(ed.y);
        float4 v = *(const float4*)&L[((size_t)ed.x << 6) + c4];
        acc.x = fmaf(v.x, w, acc.x); acc.y = fmaf(v.y, w, acc.y);
        acc.z = fmaf(v.z, w, acc.z); acc.w = fmaf(v.w, w, acc.w);
    }
    float4 o = make_float4(tanhf(acc.x), tanhf(acc.y), tanhf(acc.z), tanhf(acc.w));
    *(float4*)&Out[((size_t)node << 6) + c4] = o;
}

// ---------------- pooling (max + mean over sorted batch) + final FC ----------------
__global__ void __launch_bounds__(256) k_pool(const float* __restrict__ hfin,
                                              const int* __restrict__ batch,
                                              const float* __restrict__ Wfc,
                                              const float* __restrict__ bfc,
                                              float* __restrict__ out, int n, int O) {
    __shared__ int   sB[2];
    __shared__ float sMax[256];
    __shared__ float sSum[256];
    __shared__ float sPool[128];
    int g = blockIdx.x;
    int tid = threadIdx.x;
    if (tid < 2) {
        int tgt = g + tid;
        int lo = 0, hi = n;
        while (lo < hi) { int m = (lo + hi) >> 1; if (batch[m] < tgt) lo = m + 1; else hi = m; }
        sB[tid] = lo;
    }
    __syncthreads();
    int start = sB[0], end = sB[1];
    int col = tid & 63, grp = tid >> 6;

    float mx = __int_as_float(0xff800000);   // -inf (matches jax segment_max identity)
    float sm = 0.0f;
    for (int r = start + grp; r < end; r += 4) {
        float v = hfin[((size_t)r << 6) + col];
        mx = fmaxf(mx, v);
        sm += v;
    }
    sMax[tid] = mx; sSum[tid] = sm;
    __syncthreads();
    if (tid < 64) {
        mx = fmaxf(fmaxf(sMax[tid], sMax[tid + 64]), fmaxf(sMax[tid + 128], sMax[tid + 192]));
        sm = sSum[tid] + sSum[tid + 64] + sSum[tid + 128] + sSum[tid + 192];
        float cnt = (float)(end - start);
        sPool[tid]      = mx;                       // maxp
        sPool[64 + tid] = sm / fmaxf(cnt, 1.0f);    // meanp
    }
    __syncthreads();
    if (tid < O) {
        float acc = bfc[tid];
#pragma unroll 8
        for (int k = 0; k < 128; k++) acc = fmaf(sPool[k], Wfc[k * O + tid], acc);
        out[(size_t)g * O + tid] = acc;
    }
}

// ---------------- launch ----------------
extern "C" void kernel_launch(void* const* d_in, const int* in_sizes, int n_in,
                              void* d_out, int out_size) {
    const float* x     = (const float*)d_in[0];
    const int*   ei    = (const int*)d_in[1];     // int32: JAX x64 is disabled
    const int*   batch = (const int*)d_in[2];     // int32
    int base = n_in - 10;   // robust to optional num_graphs scalar input
    const float* W1  = (const float*)d_in[base + 0];
    const float* b1  = (const float*)d_in[base + 1];
    const float* W2  = (const float*)d_in[base + 2];
    const float* b2  = (const float*)d_in[base + 3];
    const float* W3  = (const float*)d_in[base + 4];
    const float* b3  = (const float*)d_in[base + 5];
    const float* W4  = (const float*)d_in[base + 6];
    const float* b4  = (const float*)d_in[base + 7];
    const float* Wfc = (const float*)d_in[base + 8];
    const float* bfc = (const float*)d_in[base + 9];

    const int F = 128;
    int N = in_sizes[0] / F;
    int E = in_sizes[1] / 2;
    int O = in_sizes[base + 9];
    long long NH = (long long)N * HDIM;

    float* outp = (float*)d_out;
    float* hOut = outp + ((long long)out_size - NH);   // h goes after [G,O] logits
    int G = (int)(((long long)out_size - NH) / O);

    float *bufL, *bufH;
    { void* p;
      cudaGetSymbolAddress(&p, g_bufL); bufL = (float*)p;
      cudaGetSymbolAddress(&p, g_bufH); bufH = (float*)p; }

    const int tb = 256;
    k_zero_cnt<<<(N + tb - 1) / tb, tb>>>(N);
    k_edges1 <<<(E + tb - 1) / tb, tb>>>(ei, E, N);
    k_dis    <<<(N + tb - 1) / tb, tb>>>(N);
    k_scan   <<<1, 1024>>>(N);
    k_scatter<<<(E + tb - 1) / tb, tb>>>(E);

    int gb = (N + 63) / 64;
    int ab = (N * 16 + tb - 1) / tb;
    k_gemm<128><<<gb, tb>>>(x,    W1, bufL, N);
    k_agg      <<<ab, tb>>>(bufL, b1, bufH, N);
    k_gemm<64> <<<gb, tb>>>(bufH, W2, bufL, N);
    k_agg      <<<ab, tb>>>(bufL, b2, bufH, N);
    k_gemm<64> <<<gb, tb>>>(bufH, W3, bufL, N);
    k_agg      <<<ab, tb>>>(bufL, b3, bufH, N);
    k_gemm<64> <<<gb, tb>>>(bufH, W4, bufL, N);
    k_agg      <<<ab, tb>>>(bufL, b4, hOut, N);

    k_pool<<<G, tb>>>(hOut, batch, Wfc, bfc, outp, N, O);
}

// round 3
// speedup vs baseline: 1.2987x; 1.2987x over previous
#include <cuda_runtime.h>
#include <math.h>

#define NMAX 100000
#define EMAX 3200000
#define HDIM 64
#define SCHUNK 1024                    // counts per scan block
#define SNB ((NMAX + SCHUNK - 1) / SCHUNK)

// ---------------- static device scratch (no dynamic allocation allowed) ----------------
__device__ int   g_src[EMAX];
__device__ int   g_dst[EMAX];
__device__ int2  g_cedge[EMAX];          // packed {src, norm_weight_as_int}
__device__ int   g_cnt[NMAX];
__device__ int   g_off[NMAX + 1];
__device__ int   g_pos[NMAX];
__device__ int   g_bsum[SNB + 1];
__device__ float g_dis[NMAX];
__device__ __align__(16) float g_bufL[(size_t)NMAX * HDIM];
__device__ __align__(16) float g_bufH[(size_t)NMAX * HDIM];

// ---------------- prep kernels ----------------
__global__ void k_zero_cnt(int n) {
    int i = blockIdx.x * blockDim.x + threadIdx.x;
    if (i < n) g_cnt[i] = 0;
}

// edge index is int32 (JAX x64 disabled); histogram in-degree
__global__ void k_edges1(const int* __restrict__ ei, int E, int n) {
    int e = blockIdx.x * blockDim.x + threadIdx.x;
    if (e >= E) return;
    int s = ei[e];
    int d = ei[(size_t)E + e];
    s = min(max(s, 0), n - 1);   // defensive clamp, branch-free
    d = min(max(d, 0), n - 1);
    g_src[e] = s;
    g_dst[e] = d;
    atomicAdd(&g_cnt[d], 1);
}

// deg = in_degree + 1 (self loop); dis = deg^-1/2 (deg >= 1 always)
__global__ void k_dis(int n) {
    int i = blockIdx.x * blockDim.x + threadIdx.x;
    if (i < n) g_dis[i] = rsqrtf((float)g_cnt[i] + 1.0f);
}

// ---------------- 3-pass grid-wide exclusive scan of g_cnt ----------------
// pass 1: per-block (1024 counts) sum -> g_bsum[b]
__global__ void __launch_bounds__(256) k_bsum(int n) {
    __shared__ int sred[256];
    int t = threadIdx.x;
    int base = blockIdx.x * SCHUNK + t * 4;
    int s = 0;
#pragma unroll
    for (int j = 0; j < 4; j++) {
        int i = base + j;
        if (i < n) s += g_cnt[i];
    }
    sred[t] = s;
    __syncthreads();
    for (int off = 128; off > 0; off >>= 1) {
        if (t < off) sred[t] += sred[t + off];
        __syncthreads();
    }
    if (t == 0) g_bsum[blockIdx.x] = sred[0];
}

// pass 2: one small block scans the block sums (exclusive), writes g_off[n]=total
__global__ void k_scanb(int nb, int n) {
    __shared__ int ss[SNB];
    int t = threadIdx.x;
    if (t < nb) ss[t] = g_bsum[t];
    __syncthreads();
    if (t == 0) {
        int run = 0;
        for (int b = 0; b < nb; b++) { int v = ss[b]; ss[b] = run; run += v; }
        g_off[n] = run;
    }
    __syncthreads();
    if (t < nb) g_bsum[t] = ss[t];
}

// pass 3: per-block exclusive scan of its 1024 counts + block offset -> g_off, g_pos
__global__ void __launch_bounds__(256) k_off(int n) {
    __shared__ int ssum[256];
    int t = threadIdx.x;
    int base = blockIdx.x * SCHUNK + t * 4;
    int c[4];
    int s = 0;
#pragma unroll
    for (int j = 0; j < 4; j++) {
        int i = base + j;
        c[j] = (i < n) ? g_cnt[i] : 0;
        s += c[j];
    }
    ssum[t] = s;
    __syncthreads();
    for (int off = 1; off < 256; off <<= 1) {
        int v = (t >= off) ? ssum[t - off] : 0;
        __syncthreads();
        ssum[t] += v;
        __syncthreads();
    }
    int run = g_bsum[blockIdx.x] + ssum[t] - s;   // exclusive offset for this thread's 4
#pragma unroll
    for (int j = 0; j < 4; j++) {
        int i = base + j;
        if (i < n) { g_off[i] = run; g_pos[i] = run; }
        run += c[j];
    }
}

// scatter edges into CSR-by-dst; pack src + precomputed norm weight into 8B
__global__ void k_scatter(int E) {
    int e = blockIdx.x * blockDim.x + threadIdx.x;
    if (e >= E) return;
    int s = g_src[e];
    int d = g_dst[e];
    int p = atomicAdd(&g_pos[d], 1);
    float w = g_dis[s] * g_dis[d];
    g_cedge[p] = make_int2(s, __float_as_int(w));
}

// ---------------- dense GEMM: C[n,64] = A[n,K] @ W[K,64] ----------------
// 64-row tiles, 4x4 register blocking, K chunked by 64 to stay under 48KB static smem.
template <int K>
__global__ void __launch_bounds__(256) k_gemm(const float* __restrict__ A,
                                              const float* __restrict__ W,
                                              float* __restrict__ C, int n) {
    __shared__ float Ws[K * 64];
    __shared__ float As[64 * 64];
    int tid = threadIdx.x;
    int rowBase = blockIdx.x * 64;
    for (int idx = tid; idx < K * 64; idx += 256) Ws[idx] = W[idx];

    int tc = tid & 15;       // 16 col groups of 4
    int tr = tid >> 4;       // 16 row groups of 4
    float acc[4][4];
#pragma unroll
    for (int i = 0; i < 4; i++)
#pragma unroll
        for (int j = 0; j < 4; j++) acc[i][j] = 0.0f;

    for (int kk = 0; kk < K; kk += 64) {
        __syncthreads();
        for (int idx = tid; idx < 64 * 64; idx += 256) {
            int r = idx >> 6, c = idx & 63;
            int gr = rowBase + r;
            As[idx] = (gr < n) ? A[(size_t)gr * K + kk + c] : 0.0f;
        }
        __syncthreads();
#pragma unroll 8
        for (int k2 = 0; k2 < 64; k2++) {
            float4 wv = *(const float4*)&Ws[(kk + k2) * 64 + tc * 4];
            float a0 = As[(tr * 4 + 0) * 64 + k2];
            float a1 = As[(tr * 4 + 1) * 64 + k2];
            float a2 = As[(tr * 4 + 2) * 64 + k2];
            float a3 = As[(tr * 4 + 3) * 64 + k2];
            acc[0][0] = fmaf(a0, wv.x, acc[0][0]); acc[0][1] = fmaf(a0, wv.y, acc[0][1]);
            acc[0][2] = fmaf(a0, wv.z, acc[0][2]); acc[0][3] = fmaf(a0, wv.w, acc[0][3]);
            acc[1][0] = fmaf(a1, wv.x, acc[1][0]); acc[1][1] = fmaf(a1, wv.y, acc[1][1]);
            acc[1][2] = fmaf(a1, wv.z, acc[1][2]); acc[1][3] = fmaf(a1, wv.w, acc[1][3]);
            acc[2][0] = fmaf(a2, wv.x, acc[2][0]); acc[2][1] = fmaf(a2, wv.y, acc[2][1]);
            acc[2][2] = fmaf(a2, wv.z, acc[2][2]); acc[2][3] = fmaf(a2, wv.w, acc[2][3]);
            acc[3][0] = fmaf(a3, wv.x, acc[3][0]); acc[3][1] = fmaf(a3, wv.y, acc[3][1]);
            acc[3][2] = fmaf(a3, wv.z, acc[3][2]); acc[3][3] = fmaf(a3, wv.w, acc[3][3]);
        }
    }
#pragma unroll
    for (int i = 0; i < 4; i++) {
        int gr = rowBase + tr * 4 + i;
        if (gr < n) {
            float4 o = make_float4(acc[i][0], acc[i][1], acc[i][2], acc[i][3]);
            *(float4*)&C[((size_t)gr << 6) + tc * 4] = o;
        }
    }
}

// ---------------- pull-based aggregation + bias + self-loop + tanh ----------------
// 16 lanes per node; each lane owns 4 columns (float4).
__global__ void __launch_bounds__(256) k_agg(const float* __restrict__ L,
                                             const float* __restrict__ bias,
                                             float* __restrict__ Out, int n) {
    int t = blockIdx.x * blockDim.x + threadIdx.x;
    int node = t >> 4;
    if (node >= n) return;
    int c4 = (t & 15) << 2;

    float dn = g_dis[node];
    float ws = dn * dn;
    float4 bv = *(const float4*)&bias[c4];
    float4 sv = *(const float4*)&L[((size_t)node << 6) + c4];
    float4 acc = make_float4(fmaf(sv.x, ws, bv.x), fmaf(sv.y, ws, bv.y),
                             fmaf(sv.z, ws, bv.z), fmaf(sv.w, ws, bv.w));

    int e    = g_off[node];
    int eEnd = g_off[node + 1];
    for (; e + 2 <= eEnd; e += 2) {
        int2 ed0 = g_cedge[e];
        int2 ed1 = g_cedge[e + 1];
        float w0 = __int_as_float(ed0.y);
        float w1 = __int_as_float(ed1.y);
        float4 v0 = *(const float4*)&L[((size_t)ed0.x << 6) + c4];
        float4 v1 = *(const float4*)&L[((size_t)ed1.x << 6) + c4];
        acc.x = fmaf(v0.x, w0, acc.x); acc.y = fmaf(v0.y, w0, acc.y);
        acc.z = fmaf(v0.z, w0, acc.z); acc.w = fmaf(v0.w, w0, acc.w);
        acc.x = fmaf(v1.x, w1, acc.x); acc.y = fmaf(v1.y, w1, acc.y);
        acc.z = fmaf(v1.z, w1, acc.z); acc.w = fmaf(v1.w, w1, acc.w);
    }
    if (e < eEnd) {
        int2 ed = g_cedge[e];
        float w = __int_as_float(ed.y);
        float4 v = *(const float4*)&L[((size_t)ed.x << 6) + c4];
        acc.x = fmaf(v.x, w, acc.x); acc.y = fmaf(v.y, w, acc.y);
        acc.z = fmaf(v.z, w, acc.z); acc.w = fmaf(v.w, w, acc.w);
    }
    float4 o = make_float4(tanhf(acc.x), tanhf(acc.y), tanhf(acc.z), tanhf(acc.w));
    *(float4*)&Out[((size_t)node << 6) + c4] = o;
}

// ---------------- pooling (max + mean over sorted batch) + final FC ----------------
__global__ void __launch_bounds__(256) k_pool(const float* __restrict__ hfin,
                                              const int* __restrict__ batch,
                                              const float* __restrict__ Wfc,
                                              const float* __restrict__ bfc,
                                              float* __restrict__ out, int n, int O) {
    __shared__ int   sB[2];
    __shared__ float sMax[256];
    __shared__ float sSum[256];
    __shared__ float sPool[128];
    int g = blockIdx.x;
    int tid = threadIdx.x;
    if (tid < 2) {
        int tgt = g + tid;
        int lo = 0, hi = n;
        while (lo < hi) { int m = (lo + hi) >> 1; if (batch[m] < tgt) lo = m + 1; else hi = m; }
        sB[tid] = lo;
    }
    __syncthreads();
    int start = sB[0], end = sB[1];
    int col = tid & 63, grp = tid >> 6;

    float mx = __int_as_float(0xff800000);   // -inf (matches jax segment_max identity)
    float sm = 0.0f;
    for (int r = start + grp; r < end; r += 4) {
        float v = hfin[((size_t)r << 6) + col];
        mx = fmaxf(mx, v);
        sm += v;
    }
    sMax[tid] = mx; sSum[tid] = sm;
    __syncthreads();
    if (tid < 64) {
        mx = fmaxf(fmaxf(sMax[tid], sMax[tid + 64]), fmaxf(sMax[tid + 128], sMax[tid + 192]));
        sm = sSum[tid] + sSum[tid + 64] + sSum[tid + 128] + sSum[tid + 192];
        float cnt = (float)(end - start);
        sPool[tid]      = mx;                       // maxp
        sPool[64 + tid] = sm / fmaxf(cnt, 1.0f);    // meanp
    }
    __syncthreads();
    if (tid < O) {
        float acc = bfc[tid];
#pragma unroll 8
        for (int k = 0; k < 128; k++) acc = fmaf(sPool[k], Wfc[k * O + tid], acc);
        out[(size_t)g * O + tid] = acc;
    }
}

// ---------------- launch ----------------
extern "C" void kernel_launch(void* const* d_in, const int* in_sizes, int n_in,
                              void* d_out, int out_size) {
    const float* x     = (const float*)d_in[0];
    const int*   ei    = (const int*)d_in[1];     // int32: JAX x64 is disabled
    const int*   batch = (const int*)d_in[2];     // int32
    int base = n_in - 10;   // robust to optional num_graphs scalar input
    const float* W1  = (const float*)d_in[base + 0];
    const float* b1  = (const float*)d_in[base + 1];
    const float* W2  = (const float*)d_in[base + 2];
    const float* b2  = (const float*)d_in[base + 3];
    const float* W3  = (const float*)d_in[base + 4];
    const float* b3  = (const float*)d_in[base + 5];
    const float* W4  = (const float*)d_in[base + 6];
    const float* b4  = (const float*)d_in[base + 7];
    const float* Wfc = (const float*)d_in[base + 8];
    const float* bfc = (const float*)d_in[base + 9];

    const int F = 128;
    int N = in_sizes[0] / F;
    int E = in_sizes[1] / 2;
    int O = in_sizes[base + 9];
    long long NH = (long long)N * HDIM;

    float* outp = (float*)d_out;
    float* hOut = outp + ((long long)out_size - NH);   // h goes after [G,O] logits
    int G = (int)(((long long)out_size - NH) / O);

    float *bufL, *bufH;
    { void* p;
      cudaGetSymbolAddress(&p, g_bufL); bufL = (float*)p;
      cudaGetSymbolAddress(&p, g_bufH); bufH = (float*)p; }

    const int tb = 256;
    int nb = (N + SCHUNK - 1) / SCHUNK;
    k_zero_cnt<<<(N + tb - 1) / tb, tb>>>(N);
    k_edges1 <<<(E + tb - 1) / tb, tb>>>(ei, E, N);
    k_dis    <<<(N + tb - 1) / tb, tb>>>(N);
    k_bsum   <<<nb, tb>>>(N);
    k_scanb  <<<1, ((nb + 31) / 32) * 32>>>(nb, N);
    k_off    <<<nb, tb>>>(N);
    k_scatter<<<(E + tb - 1) / tb, tb>>>(E);

    int gb = (N + 63) / 64;
    int ab = (N * 16 + tb - 1) / tb;
    k_gemm<128><<<gb, tb>>>(x,    W1, bufL, N);
    k_agg      <<<ab, tb>>>(bufL, b1, bufH, N);
    k_gemm<64> <<<gb, tb>>>(bufH, W2, bufL, N);
    k_agg      <<<ab, tb>>>(bufL, b2, bufH, N);
    k_gemm<64> <<<gb, tb>>>(bufH, W3, bufL, N);
    k_agg      <<<ab, tb>>>(bufL, b3, bufH, N);
    k_gemm<64> <<<gb, tb>>>(bufH, W4, bufL, N);
    k_agg      <<<ab, tb>>>(bufL, b4, hOut, N);

    k_pool<<<G, tb>>>(hOut, batch, Wfc, bfc, outp, N, O);
}

// round 4
// speedup vs baseline: 1.4624x; 1.1260x over previous
#include <cuda_runtime.h>
#include <math.h>

#define NMAX 100000
#define EMAX 3200000
#define HDIM 64
#define SCHUNK 1024                    // counts per scan block
#define SNB ((NMAX + SCHUNK - 1) / SCHUNK)

// ---------------- static device scratch (no dynamic allocation allowed) ----------------
__device__ int2  g_sd[EMAX];             // packed {src, dst}
__device__ int2  g_cedge[EMAX];          // packed {src, norm_weight_as_int}
__device__ int   g_cnt[NMAX];
__device__ int   g_off[NMAX + 1];
__device__ int   g_pos[NMAX];
__device__ int   g_bsum[SNB + 1];
__device__ float g_dis[NMAX];
__device__ __align__(16) float g_bufL[(size_t)NMAX * HDIM];
__device__ __align__(16) float g_bufH[(size_t)NMAX * HDIM];

// ---------------- prep kernels ----------------
__global__ void k_zero_cnt(int n) {
    int i = blockIdx.x * blockDim.x + threadIdx.x;
    if (i < n) g_cnt[i] = 0;
}

// edge index is int32 (JAX x64 disabled); histogram in-degree
__global__ void k_edges1(const int* __restrict__ ei, int E, int n) {
    int e = blockIdx.x * blockDim.x + threadIdx.x;
    if (e >= E) return;
    int s = ei[e];
    int d = ei[(size_t)E + e];
    s = min(max(s, 0), n - 1);   // defensive clamp, branch-free
    d = min(max(d, 0), n - 1);
    g_sd[e] = make_int2(s, d);
    atomicAdd(&g_cnt[d], 1);
}

// deg = in_degree + 1 (self loop); dis = deg^-1/2 (deg >= 1 always)
__global__ void k_dis(int n) {
    int i = blockIdx.x * blockDim.x + threadIdx.x;
    if (i < n) g_dis[i] = rsqrtf((float)g_cnt[i] + 1.0f);
}

// ---------------- 3-pass grid-wide exclusive scan of g_cnt ----------------
__global__ void __launch_bounds__(256) k_bsum(int n) {
    __shared__ int sred[256];
    int t = threadIdx.x;
    int base = blockIdx.x * SCHUNK + t * 4;
    int s = 0;
#pragma unroll
    for (int j = 0; j < 4; j++) {
        int i = base + j;
        if (i < n) s += g_cnt[i];
    }
    sred[t] = s;
    __syncthreads();
    for (int off = 128; off > 0; off >>= 1) {
        if (t < off) sred[t] += sred[t + off];
        __syncthreads();
    }
    if (t == 0) g_bsum[blockIdx.x] = sred[0];
}

__global__ void k_scanb(int nb, int n) {
    __shared__ int ss[SNB];
    int t = threadIdx.x;
    if (t < nb) ss[t] = g_bsum[t];
    __syncthreads();
    if (t == 0) {
        int run = 0;
        for (int b = 0; b < nb; b++) { int v = ss[b]; ss[b] = run; run += v; }
        g_off[n] = run;
    }
    __syncthreads();
    if (t < nb) g_bsum[t] = ss[t];
}

__global__ void __launch_bounds__(256) k_off(int n) {
    __shared__ int ssum[256];
    int t = threadIdx.x;
    int base = blockIdx.x * SCHUNK + t * 4;
    int c[4];
    int s = 0;
#pragma unroll
    for (int j = 0; j < 4; j++) {
        int i = base + j;
        c[j] = (i < n) ? g_cnt[i] : 0;
        s += c[j];
    }
    ssum[t] = s;
    __syncthreads();
    for (int off = 1; off < 256; off <<= 1) {
        int v = (t >= off) ? ssum[t - off] : 0;
        __syncthreads();
        ssum[t] += v;
        __syncthreads();
    }
    int run = g_bsum[blockIdx.x] + ssum[t] - s;
#pragma unroll
    for (int j = 0; j < 4; j++) {
        int i = base + j;
        if (i < n) { g_off[i] = run; g_pos[i] = run; }
        run += c[j];
    }
}

// scatter edges into CSR-by-dst; pack src + precomputed norm weight into 8B
__global__ void k_scatter(int E) {
    int e = blockIdx.x * blockDim.x + threadIdx.x;
    if (e >= E) return;
    int2 sd = g_sd[e];
    int p = atomicAdd(&g_pos[sd.y], 1);
    float w = g_dis[sd.x] * g_dis[sd.y];
    g_cedge[p] = make_int2(sd.x, __float_as_int(w));
}

// ---------------- dense GEMM: C[n,64] = A[n,K] @ W[K,64] ----------------
// 128-row tiles, 8x4 register blocking, K chunked by 32, A staged transposed in smem.
// Inner loop: 3 x LDS.128 per 32 FMA -> FMA-pipe bound.
template <int K>
__global__ void __launch_bounds__(256) k_gemm(const float* __restrict__ A,
                                              const float* __restrict__ W,
                                              float* __restrict__ C, int n) {
    __shared__ float As[32][132];     // [k][row], stride 132 keeps 16B align + bank spread
    __shared__ float Ws[32][64];
    int tid = threadIdx.x;
    int rowBase = blockIdx.x * 128;
    int tc = tid & 15;                // 16 col groups of 4
    int tr = tid >> 4;                // 16 row groups of 8

    float acc[8][4];
#pragma unroll
    for (int i = 0; i < 8; i++)
#pragma unroll
        for (int j = 0; j < 4; j++) acc[i][j] = 0.0f;

    for (int kk = 0; kk < K; kk += 32) {
        __syncthreads();
        // Ws: 32x64 floats = 512 float4, 2 per thread
#pragma unroll
        for (int i = tid; i < 512; i += 256) {
            ((float4*)Ws)[i] = *(const float4*)&W[(kk + (i >> 4)) * 64 + (i & 15) * 4];
        }
        // As (transposed): 128 rows x 32 k = 1024 float4 reads, 4 per thread
#pragma unroll
        for (int i = tid; i < 1024; i += 256) {
            int r  = i >> 3;          // 8 float4 per row
            int k4 = i & 7;
            int gr = rowBase + r;
            float4 v = (gr < n) ? *(const float4*)&A[(size_t)gr * K + kk + k4 * 4]
                                : make_float4(0.f, 0.f, 0.f, 0.f);
            As[k4 * 4 + 0][r] = v.x;
            As[k4 * 4 + 1][r] = v.y;
            As[k4 * 4 + 2][r] = v.z;
            As[k4 * 4 + 3][r] = v.w;
        }
        __syncthreads();
#pragma unroll
        for (int k2 = 0; k2 < 32; k2++) {
            float4 wv  = *(const float4*)&Ws[k2][tc * 4];
            float4 aLo = *(const float4*)&As[k2][tr * 8];
            float4 aHi = *(const float4*)&As[k2][tr * 8 + 4];
            float a[8] = {aLo.x, aLo.y, aLo.z, aLo.w, aHi.x, aHi.y, aHi.z, aHi.w};
#pragma unroll
            for (int i = 0; i < 8; i++) {
                acc[i][0] = fmaf(a[i], wv.x, acc[i][0]);
                acc[i][1] = fmaf(a[i], wv.y, acc[i][1]);
                acc[i][2] = fmaf(a[i], wv.z, acc[i][2]);
                acc[i][3] = fmaf(a[i], wv.w, acc[i][3]);
            }
        }
    }
#pragma unroll
    for (int i = 0; i < 8; i++) {
        int gr = rowBase + tr * 8 + i;
        if (gr < n) {
            float4 o = make_float4(acc[i][0], acc[i][1], acc[i][2], acc[i][3]);
            *(float4*)&C[((size_t)gr << 6) + tc * 4] = o;
        }
    }
}

// ---------------- pull-based aggregation + bias + self-loop + tanh ----------------
// 16 lanes per node; each lane owns 4 columns (float4). 4-wide edge unroll (MLP=4).
__global__ void __launch_bounds__(256) k_agg(const float* __restrict__ L,
                                             const float* __restrict__ bias,
                                             float* __restrict__ Out, int n) {
    int t = blockIdx.x * blockDim.x + threadIdx.x;
    int node = t >> 4;
    if (node >= n) return;
    int c4 = (t & 15) << 2;

    float dn = g_dis[node];
    float ws = dn * dn;
    float4 bv = *(const float4*)&bias[c4];
    float4 sv = *(const float4*)&L[((size_t)node << 6) + c4];
    float4 acc = make_float4(fmaf(sv.x, ws, bv.x), fmaf(sv.y, ws, bv.y),
                             fmaf(sv.z, ws, bv.z), fmaf(sv.w, ws, bv.w));

    int e    = g_off[node];
    int eEnd = g_off[node + 1];
    for (; e + 4 <= eEnd; e += 4) {
        int2 ed0 = g_cedge[e];
        int2 ed1 = g_cedge[e + 1];
        int2 ed2 = g_cedge[e + 2];
        int2 ed3 = g_cedge[e + 3];
        float4 v0 = *(const float4*)&L[((size_t)ed0.x << 6) + c4];
        float4 v1 = *(const float4*)&L[((size_t)ed1.x << 6) + c4];
        float4 v2 = *(const float4*)&L[((size_t)ed2.x << 6) + c4];
        float4 v3 = *(const float4*)&L[((size_t)ed3.x << 6) + c4];
        float w0 = __int_as_float(ed0.y), w1 = __int_as_float(ed1.y);
        float w2 = __int_as_float(ed2.y), w3 = __int_as_float(ed3.y);
        acc.x = fmaf(v0.x, w0, acc.x); acc.y = fmaf(v0.y, w0, acc.y);
        acc.z = fmaf(v0.z, w0, acc.z); acc.w = fmaf(v0.w, w0, acc.w);
        acc.x = fmaf(v1.x, w1, acc.x); acc.y = fmaf(v1.y, w1, acc.y);
        acc.z = fmaf(v1.z, w1, acc.z); acc.w = fmaf(v1.w, w1, acc.w);
        acc.x = fmaf(v2.x, w2, acc.x); acc.y = fmaf(v2.y, w2, acc.y);
        acc.z = fmaf(v2.z, w2, acc.z); acc.w = fmaf(v2.w, w2, acc.w);
        acc.x = fmaf(v3.x, w3, acc.x); acc.y = fmaf(v3.y, w3, acc.y);
        acc.z = fmaf(v3.z, w3, acc.z); acc.w = fmaf(v3.w, w3, acc.w);
    }
    for (; e < eEnd; e++) {
        int2 ed = g_cedge[e];
        float w = __int_as_float(ed.y);
        float4 v = *(const float4*)&L[((size_t)ed.x << 6) + c4];
        acc.x = fmaf(v.x, w, acc.x); acc.y = fmaf(v.y, w, acc.y);
        acc.z = fmaf(v.z, w, acc.z); acc.w = fmaf(v.w, w, acc.w);
    }
    float4 o = make_float4(tanhf(acc.x), tanhf(acc.y), tanhf(acc.z), tanhf(acc.w));
    *(float4*)&Out[((size_t)node << 6) + c4] = o;
}

// ---------------- pooling (max + mean over sorted batch) + final FC ----------------
__global__ void __launch_bounds__(256) k_pool(const float* __restrict__ hfin,
                                              const int* __restrict__ batch,
                                              const float* __restrict__ Wfc,
                                              const float* __restrict__ bfc,
                                              float* __restrict__ out, int n, int O) {
    __shared__ int   sB[2];
    __shared__ float sMax[256];
    __shared__ float sSum[256];
    __shared__ float sPool[128];
    int g = blockIdx.x;
    int tid = threadIdx.x;
    if (tid < 2) {
        int tgt = g + tid;
        int lo = 0, hi = n;
        while (lo < hi) { int m = (lo + hi) >> 1; if (batch[m] < tgt) lo = m + 1; else hi = m; }
        sB[tid] = lo;
    }
    __syncthreads();
    int start = sB[0], end = sB[1];
    int col = tid & 63, grp = tid >> 6;

    float mx = __int_as_float(0xff800000);   // -inf (matches jax segment_max identity)
    float sm = 0.0f;
    for (int r = start + grp; r < end; r += 4) {
        float v = hfin[((size_t)r << 6) + col];
        mx = fmaxf(mx, v);
        sm += v;
    }
    sMax[tid] = mx; sSum[tid] = sm;
    __syncthreads();
    if (tid < 64) {
        mx = fmaxf(fmaxf(sMax[tid], sMax[tid + 64]), fmaxf(sMax[tid + 128], sMax[tid + 192]));
        sm = sSum[tid] + sSum[tid + 64] + sSum[tid + 128] + sSum[tid + 192];
        float cnt = (float)(end - start);
        sPool[tid]      = mx;                       // maxp
        sPool[64 + tid] = sm / fmaxf(cnt, 1.0f);    // meanp
    }
    __syncthreads();
    if (tid < O) {
        float acc = bfc[tid];
#pragma unroll 8
        for (int k = 0; k < 128; k++) acc = fmaf(sPool[k], Wfc[k * O + tid], acc);
        out[(size_t)g * O + tid] = acc;
    }
}

// ---------------- launch ----------------
extern "C" void kernel_launch(void* const* d_in, const int* in_sizes, int n_in,
                              void* d_out, int out_size) {
    const float* x     = (const float*)d_in[0];
    const int*   ei    = (const int*)d_in[1];     // int32: JAX x64 is disabled
    const int*   batch = (const int*)d_in[2];     // int32
    int base = n_in - 10;
    const float* W1  = (const float*)d_in[base + 0];
    const float* b1  = (const float*)d_in[base + 1];
    const float* W2  = (const float*)d_in[base + 2];
    const float* b2  = (const float*)d_in[base + 3];
    const float* W3  = (const float*)d_in[base + 4];
    const float* b3  = (const float*)d_in[base + 5];
    const float* W4  = (const float*)d_in[base + 6];
    const float* b4  = (const float*)d_in[base + 7];
    const float* Wfc = (const float*)d_in[base + 8];
    const float* bfc = (const float*)d_in[base + 9];

    const int F = 128;
    int N = in_sizes[0] / F;
    int E = in_sizes[1] / 2;
    int O = in_sizes[base + 9];
    long long NH = (long long)N * HDIM;

    float* outp = (float*)d_out;
    float* hOut = outp + ((long long)out_size - NH);   // h goes after [G,O] logits
    int G = (int)(((long long)out_size - NH) / O);

    float *bufL, *bufH;
    { void* p;
      cudaGetSymbolAddress(&p, g_bufL); bufL = (float*)p;
      cudaGetSymbolAddress(&p, g_bufH); bufH = (float*)p; }

    // persistent side stream + events (created once, on the first/correctness call,
    // outside graph capture; no device memory is allocated here)
    static cudaStream_t sPrep = nullptr;
    static cudaEvent_t  evRoot = nullptr, evPrep = nullptr;
    if (sPrep == nullptr) {
        cudaStreamCreateWithFlags(&sPrep, cudaStreamNonBlocking);
        cudaEventCreateWithFlags(&evRoot, cudaEventDisableTiming);
        cudaEventCreateWithFlags(&evPrep, cudaEventDisableTiming);
    }

    const int tb = 256;
    int nb = (N + SCHUNK - 1) / SCHUNK;

    // fork: CSR build on sPrep, concurrent with GEMM1 on the main stream
    cudaEventRecord(evRoot, 0);
    cudaStreamWaitEvent(sPrep, evRoot, 0);
    k_zero_cnt<<<(N + tb - 1) / tb, tb, 0, sPrep>>>(N);
    k_edges1 <<<(E + tb - 1) / tb, tb, 0, sPrep>>>(ei, E, N);
    k_dis    <<<(N + tb - 1) / tb, tb, 0, sPrep>>>(N);
    k_bsum   <<<nb, tb, 0, sPrep>>>(N);
    k_scanb  <<<1, ((nb + 31) / 32) * 32, 0, sPrep>>>(nb, N);
    k_off    <<<nb, tb, 0, sPrep>>>(N);
    k_scatter<<<(E + tb - 1) / tb, tb, 0, sPrep>>>(E);
    cudaEventRecord(evPrep, sPrep);

    int gb = (N + 127) / 128;
    int ab = (N * 16 + tb - 1) / tb;
    k_gemm<128><<<gb, tb>>>(x, W1, bufL, N);     // independent of CSR build
    cudaStreamWaitEvent(0, evPrep, 0);           // join before first aggregation

    k_agg      <<<ab, tb>>>(bufL, b1, bufH, N);
    k_gemm<64> <<<gb, tb>>>(bufH, W2, bufL, N);
    k_agg      <<<ab, tb>>>(bufL, b2, bufH, N);
    k_gemm<64> <<<gb, tb>>>(bufH, W3, bufL, N);
    k_agg      <<<ab, tb>>>(bufL, b3, bufH, N);
    k_gemm<64> <<<gb, tb>>>(bufH, W4, bufL, N);
    k_agg      <<<ab, tb>>>(bufL, b4, hOut, N);

    k_pool<<<G, tb>>>(hOut, batch, Wfc, bfc, outp, N, O);
}